// round 5
// baseline (speedup 1.0000x reference)
#include <cuda_runtime.h>
#include <cuda_bf16.h>

constexpr int N_ELEC = 8192;
constexpr int DIM    = 256;
constexpr int NNB    = 24;
constexpr int F0     = 32;
constexpr int F1     = 16;
constexpr int NENV   = 8;
constexpr float CUTOFF = 5.0f;

__device__ float g_elec1[N_ELEC * DIM];
__device__ float g_hmsg [N_ELEC * DIM];
__device__ float g_t1   [N_ELEC * DIM];
__device__ float g_t2   [N_ELEC * DIM];

typedef unsigned long long u64;

__device__ __forceinline__ u64 pk2(float x, float y) {
    u64 r; asm("mov.b64 %0, {%1,%2};" : "=l"(r) : "f"(x), "f"(y)); return r;
}
__device__ __forceinline__ float2 upk2(u64 v) {
    float2 f; asm("mov.b64 {%0,%1}, %2;" : "=f"(f.x), "=f"(f.y) : "l"(v)); return f;
}
__device__ __forceinline__ u64 f2fma(u64 a, u64 b, u64 c) {
    u64 d; asm("fma.rn.f32x2 %0, %1, %2, %3;" : "=l"(d) : "l"(a), "l"(b), "l"(c));
    return d;
}

__device__ __forceinline__ float silu_f(float x) {
    float e = __expf(-x);
    return __fdividef(x, 1.0f + e);
}

// ---------------------------------------------------------------------------
// GEMM: out[8192,256] = epilogue(A[8192,256] @ W[256,256])
// BM=64, BN=32, BK=16, 128 threads, thread tile 4x4 (2 row-pairs x 4 cols),
// f32x2 FMA, double-buffered SMEM, grid 1024 blocks (occ ~43%).
// MODE 0: silu(acc+bias)   MODE 1: silu(acc+bias+extra)
// MODE 2: (silu(acc+bias)+res)*scale
// ---------------------------------------------------------------------------
template <int MODE>
__global__ __launch_bounds__(128) void gemm_silu(
    const float* __restrict__ A, const float* __restrict__ W,
    const float* __restrict__ bias, const float* __restrict__ extra,
    const float* __restrict__ res, const float* __restrict__ scale_p,
    float* __restrict__ out)
{
    __shared__ __align__(16) float As[2][16][64];   // [buf][k][m]
    __shared__ __align__(16) float Bs[2][16][32];   // [buf][k][n]

    const int tid = threadIdx.x;
    const int bm  = blockIdx.y;   // 128 tiles of 64 rows
    const int bn  = blockIdx.x;   // 8 tiles of 32 cols

    const int tx = tid & 7;       // col group: cols tx*4 .. +3
    const int ty = tid >> 3;      // row group: rows ty*4 .. +3  (0..15)

    // A staging: 2 threads per row; conflict-free STS (lane-major rows)
    const int arow = tid & 63;          // 0..63
    const int acol = (tid >> 6) * 8;    // 0 or 8
    // B staging: one float4 per thread
    const int brow = tid >> 3;          // 0..15
    const int bcol = (tid & 7) * 4;     // 0..28

    const float* Ag = A + (size_t)(bm * 64 + arow) * DIM + acol;
    const float* Wg = W + (size_t)brow * DIM + bn * 32 + bcol;

    u64 acc[2][4];
#pragma unroll
    for (int i = 0; i < 2; i++)
#pragma unroll
        for (int j = 0; j < 4; j++) acc[i][j] = 0ull;

    float4 pa0, pa1, pb0;
    pa0 = *(const float4*)(Ag);
    pa1 = *(const float4*)(Ag + 4);
    pb0 = *(const float4*)(Wg);

    {
        float a[8] = { pa0.x, pa0.y, pa0.z, pa0.w, pa1.x, pa1.y, pa1.z, pa1.w };
#pragma unroll
        for (int j = 0; j < 8; j++) As[0][acol + j][arow] = a[j];
        *(float4*)&Bs[0][brow][bcol] = pb0;
    }
    __syncthreads();

    int buf = 0;
    for (int k0 = 0; k0 < DIM; k0 += 16) {
        const bool more = (k0 + 16 < DIM);
        if (more) {
            pa0 = *(const float4*)(Ag + k0 + 16);
            pa1 = *(const float4*)(Ag + k0 + 16 + 4);
            pb0 = *(const float4*)(Wg + (size_t)(k0 + 16) * DIM);
        }

#pragma unroll
        for (int kk = 0; kk < 16; kk++) {
            ulonglong2 av = *(const ulonglong2*)&As[buf][kk][ty * 4];
            float4 bv = *(const float4*)&Bs[buf][kk][tx * 4];
            u64 a2[2] = { av.x, av.y };
            u64 b2[4] = { pk2(bv.x, bv.x), pk2(bv.y, bv.y),
                          pk2(bv.z, bv.z), pk2(bv.w, bv.w) };
#pragma unroll
            for (int i = 0; i < 2; i++)
#pragma unroll
                for (int j = 0; j < 4; j++)
                    acc[i][j] = f2fma(a2[i], b2[j], acc[i][j]);
        }

        if (more) {
            float a[8] = { pa0.x, pa0.y, pa0.z, pa0.w, pa1.x, pa1.y, pa1.z, pa1.w };
#pragma unroll
            for (int j = 0; j < 8; j++) As[buf ^ 1][acol + j][arow] = a[j];
            *(float4*)&Bs[buf ^ 1][brow][bcol] = pb0;
        }
        __syncthreads();
        buf ^= 1;
    }

    // unpack accumulators: acc[i][j] -> rows (ty*4+2i, +1), col tx*4+j
    float v[4][4];
#pragma unroll
    for (int i = 0; i < 2; i++)
#pragma unroll
        for (int j = 0; j < 4; j++) {
            float2 t = upk2(acc[i][j]);
            v[2 * i + 0][j] = t.x;
            v[2 * i + 1][j] = t.y;
        }

    const int col0 = bn * 32 + tx * 4;
    float sc = 1.0f;
    if (MODE == 2) sc = *scale_p;
    float4 bv = *(const float4*)(bias + col0);
    float bb[4] = { bv.x, bv.y, bv.z, bv.w };

#pragma unroll
    for (int rr = 0; rr < 4; rr++) {
        const int row = bm * 64 + ty * 4 + rr;
        const size_t off = (size_t)row * DIM + col0;
        float w[4];
#pragma unroll
        for (int j = 0; j < 4; j++) w[j] = v[rr][j] + bb[j];
        if (MODE == 1) {
            float4 e = *(const float4*)(extra + off);
            w[0] += e.x; w[1] += e.y; w[2] += e.z; w[3] += e.w;
        }
        float o[4];
#pragma unroll
        for (int j = 0; j < 4; j++) o[j] = silu_f(w[j]);
        if (MODE == 2) {
            float4 rv = *(const float4*)(res + off);
            o[0] = (o[0] + rv.x) * sc; o[1] = (o[1] + rv.y) * sc;
            o[2] = (o[2] + rv.z) * sc; o[3] = (o[3] + rv.w) * sc;
        }
        *(float4*)(out + off) = make_float4(o[0], o[1], o[2], o[3]);
    }
}

// ---------------------------------------------------------------------------
// Pair kernel: 8 electrons per block, 256 threads.
// Phase 2 uses warp-uniform pointer select (Wsame vs Wdiff columns in SMEM)
// so each k costs a single 16-wide dot (9 f2fma).
// ---------------------------------------------------------------------------
constexpr int NPB   = 8;
constexpr int PAIRS = NPB * NNB;   // 192

__global__ __launch_bounds__(256) void pair_kernel(
    const float* __restrict__ elec1,
    const float* __restrict__ r,
    const float* __restrict__ r_nb,
    const int*   __restrict__ s,
    const int*   __restrict__ s_nb,
    const float* __restrict__ hinit_nb,
    const float* __restrict__ ee_scales,
    const float* __restrict__ ee_kernel,
    const float* __restrict__ ee_bias,
    const float* __restrict__ Wf,
    const float* __restrict__ bf,
    const float* __restrict__ Wsame,
    const float* __restrict__ Wdiff,
    float* __restrict__ hinit_msg)
{
    __shared__ __align__(16) float beta_s[PAIRS][F1];   // 12 KB
    __shared__ int  mask_s[PAIRS];
    __shared__ u64  ws2_s[8][DIM];                      // 16 KB (Wsame pairs)
    __shared__ u64  wd2_s[8][DIM];                      // 16 KB (Wdiff pairs)
    __shared__ float eek_s[4 * F0];
    __shared__ float eeb_s[F0];
    __shared__ float wf_s[(F0 + NENV) * F1];
    __shared__ float bfv_s[F1];
    __shared__ float scl_s[NENV];

    const int tid = threadIdx.x;
    const int n0  = blockIdx.x * NPB;

    for (int i = tid; i < 4 * F0; i += 256) eek_s[i] = ee_kernel[i];
    for (int i = tid; i < F0; i += 256)     eeb_s[i] = ee_bias[i];
    for (int i = tid; i < (F0 + NENV) * F1; i += 256) wf_s[i] = Wf[i];
    if (tid < F1)   bfv_s[tid] = bf[tid];
    if (tid < NENV) scl_s[tid] = ee_scales[tid];

#pragma unroll
    for (int i = 0; i < 8; i++) {
        ws2_s[i][tid] = pk2(Wsame[(2 * i) * DIM + tid], Wsame[(2 * i + 1) * DIM + tid]);
        wd2_s[i][tid] = pk2(Wdiff[(2 * i) * DIM + tid], Wdiff[(2 * i + 1) * DIM + tid]);
    }
    __syncthreads();

    // ---- Phase 1: per-pair beta (threads 0..191) ----
    if (tid < PAIRS) {
        const int nl = tid / NNB;
        const int k  = tid % NNB;
        const int n  = n0 + nl;

        const float rx = r[n * 3 + 0];
        const float ry = r[n * 3 + 1];
        const float rz = r[n * 3 + 2];
        const float* rn = r_nb + (size_t)(n * NNB + k) * 3;
        const float dx = rn[0] - rx;
        const float dy = rn[1] - ry;
        const float dz = rn[2] - rz;
        const float dist = sqrtf(dx * dx + dy * dy + dz * dz + 1e-12f);

        float feats[4] = { dist, dx, dy, dz };
        float h[F0];
#pragma unroll
        for (int j = 0; j < F0; j++) {
            float t = eeb_s[j];
#pragma unroll
            for (int f = 0; f < 4; f++) t += feats[f] * eek_s[f * F0 + j];
            h[j] = silu_f(t);
        }
        float env[NENV];
#pragma unroll
        for (int e = 0; e < NENV; e++) {
            float q = __fdividef(dist, scl_s[e]);
            env[e] = __expf(-q * q);
        }
        const float xx  = dist * (1.0f / CUTOFF);
        const float cut = (dist < CUTOFF)
                        ? (1.0f - xx) * (1.0f - xx) * (1.0f + 2.0f * xx)
                        : 0.0f;
#pragma unroll
        for (int i = 0; i < F1; i++) {
            float b = bfv_s[i];
#pragma unroll
            for (int j = 0; j < F0; j++)   b += h[j]   * wf_s[j * F1 + i];
#pragma unroll
            for (int e = 0; e < NENV; e++) b += env[e] * wf_s[(F0 + e) * F1 + i];
            beta_s[tid][i] = b * cut;
        }
        mask_s[tid] = (s[n] == s_nb[n * NNB + k]) ? 1 : 0;
    }
    __syncthreads();

    // ---- Phase 2: per-channel reduction (thread d = 0..255) ----
    const int d = tid;
    const u64* ws_col = &ws2_s[0][d];
    const u64* wd_col = &wd2_s[0][d];

    for (int nl = 0; nl < NPB; nl++) {
        const int n = n0 + nl;
        const float e1 = elec1[(size_t)n * DIM + d];
        const float* hb = hinit_nb + ((size_t)n * NNB) * DIM + d;

        // batch all 24 neighbor loads then silu
        float uu[NNB];
#pragma unroll
        for (int k = 0; k < NNB; k++) uu[k] = e1 + hb[(size_t)k * DIM];
#pragma unroll
        for (int k = 0; k < NNB; k++) uu[k] = silu_f(uu[k]);

        u64 r2 = 0ull;
#pragma unroll
        for (int k = 0; k < NNB; k++) {
            const int pair = nl * NNB + k;
            // warp-uniform select of the weight column
            const u64* wp = mask_s[pair] ? ws_col : wd_col;
            const u64* bp = (const u64*)beta_s[pair];
            u64 dp = 0ull;
#pragma unroll
            for (int i = 0; i < 8; i++)
                dp = f2fma(bp[i], wp[(size_t)i * DIM], dp);
            r2 = f2fma(pk2(uu[k], uu[k]), dp, r2);
        }
        float2 rr = upk2(r2);
        hinit_msg[(size_t)n * DIM + d] = rr.x + rr.y;
    }
}

// ---------------------------------------------------------------------------
extern "C" void kernel_launch(void* const* d_in, const int* in_sizes, int n_in,
                              void* d_out, int out_size)
{
    const float* elec     = (const float*)d_in[0];
    const float* msg      = (const float*)d_in[1];
    const float* r        = (const float*)d_in[2];
    const float* r_nb     = (const float*)d_in[3];
    const int*   s        = (const int*)  d_in[4];
    const int*   s_nb     = (const int*)  d_in[5];
    const float* hinit_nb = (const float*)d_in[6];
    const float* W_in     = (const float*)d_in[7];
    const float* b_in     = (const float*)d_in[8];
    const float* ee_scales= (const float*)d_in[9];
    const float* ee_kernel= (const float*)d_in[10];
    const float* ee_bias  = (const float*)d_in[11];
    const float* Wf       = (const float*)d_in[12];
    const float* bf       = (const float*)d_in[13];
    const float* Wsame    = (const float*)d_in[14];
    const float* Wdiff    = (const float*)d_in[15];
    const float* W1       = (const float*)d_in[16];
    const float* b1       = (const float*)d_in[17];
    const float* W2       = (const float*)d_in[18];
    const float* b2       = (const float*)d_in[19];
    const float* W3       = (const float*)d_in[20];
    const float* b3       = (const float*)d_in[21];
    const float* scale    = (const float*)d_in[22];

    float* out = (float*)d_out;

    float *elec1, *hmsg, *t1, *t2;
    cudaGetSymbolAddress((void**)&elec1, g_elec1);
    cudaGetSymbolAddress((void**)&hmsg,  g_hmsg);
    cudaGetSymbolAddress((void**)&t1,    g_t1);
    cudaGetSymbolAddress((void**)&t2,    g_t2);

    dim3 ggrid(DIM / 32, N_ELEC / 64);   // (8, 128) = 1024 blocks
    dim3 gblk(128);

    gemm_silu<0><<<ggrid, gblk>>>(elec, W_in, b_in, nullptr, nullptr, nullptr, elec1);

    pair_kernel<<<N_ELEC / NPB, 256>>>(elec1, r, r_nb, s, s_nb, hinit_nb,
                                       ee_scales, ee_kernel, ee_bias, Wf, bf,
                                       Wsame, Wdiff, hmsg);

    gemm_silu<1><<<ggrid, gblk>>>(elec1, W1, b1, hmsg, nullptr, nullptr, t1);
    gemm_silu<1><<<ggrid, gblk>>>(t1, W2, b2, msg, nullptr, nullptr, t2);
    gemm_silu<2><<<ggrid, gblk>>>(t2, W3, b3, nullptr, elec1, scale, out);
}

// round 7
// speedup vs baseline: 1.5761x; 1.5761x over previous
#include <cuda_runtime.h>
#include <cuda_bf16.h>
#include <cstdint>

typedef unsigned long long u64;
typedef unsigned int u32;

constexpr int N_ELEC = 8192;
constexpr int DIM    = 256;
constexpr int NNB    = 24;
constexpr int F0     = 32;
constexpr int F1     = 16;
constexpr int NENV   = 8;
constexpr float CUTOFF = 5.0f;

// ---------------- scratch (device globals; no allocation) ----------------
__device__ float g_e1  [N_ELEC * DIM];
__device__ float g_hmsg[N_ELEC * DIM];
__device__ __nv_bfloat16 g_eh [N_ELEC * DIM], g_el [N_ELEC * DIM];
__device__ __nv_bfloat16 g_e1h[N_ELEC * DIM], g_e1l[N_ELEC * DIM];
__device__ __nv_bfloat16 g_t1h[N_ELEC * DIM], g_t1l[N_ELEC * DIM];
__device__ __nv_bfloat16 g_t2h[N_ELEC * DIM], g_t2l[N_ELEC * DIM];
__device__ __nv_bfloat16 g_w0h[DIM * DIM], g_w0l[DIM * DIM];
__device__ __nv_bfloat16 g_w1h[DIM * DIM], g_w1l[DIM * DIM];
__device__ __nv_bfloat16 g_w2h[DIM * DIM], g_w2l[DIM * DIM];
__device__ __nv_bfloat16 g_w3h[DIM * DIM], g_w3l[DIM * DIM];

// ---------------- helpers ----------------
__device__ __forceinline__ u64 pk2(float x, float y) {
    u64 r; asm("mov.b64 %0, {%1,%2};" : "=l"(r) : "f"(x), "f"(y)); return r;
}
__device__ __forceinline__ float2 upk2(u64 v) {
    float2 f; asm("mov.b64 {%0,%1}, %2;" : "=f"(f.x), "=f"(f.y) : "l"(v)); return f;
}
__device__ __forceinline__ u64 f2fma(u64 a, u64 b, u64 c) {
    u64 d; asm("fma.rn.f32x2 %0, %1, %2, %3;" : "=l"(d) : "l"(a), "l"(b), "l"(c));
    return d;
}
__device__ __forceinline__ float silu_f(float x) {
    float e = __expf(-x);
    return __fdividef(x, 1.0f + e);
}

// bf16 mma: D(16x8 f32) += A(16x16 bf16, row) * B(16x8 bf16, col)
__device__ __forceinline__ void mma_bf16(
    float c[4], u32 a0, u32 a1, u32 a2, u32 a3, u32 b0, u32 b1)
{
    asm volatile(
        "mma.sync.aligned.m16n8k16.row.col.f32.bf16.bf16.f32 "
        "{%0,%1,%2,%3}, {%4,%5,%6,%7}, {%8,%9}, {%0,%1,%2,%3};"
        : "+f"(c[0]), "+f"(c[1]), "+f"(c[2]), "+f"(c[3])
        : "r"(a0), "r"(a1), "r"(a2), "r"(a3), "r"(b0), "r"(b1));
}

// ---------------- prep kernels ----------------
__global__ __launch_bounds__(256) void split_f32(
    const float* __restrict__ x, __nv_bfloat16* __restrict__ h,
    __nv_bfloat16* __restrict__ l, int n4)
{
    int i = blockIdx.x * 256 + threadIdx.x;
    if (i >= n4) return;
    float4 v = ((const float4*)x)[i];
    float vv[4] = { v.x, v.y, v.z, v.w };
    __nv_bfloat16 hh[4], ll[4];
#pragma unroll
    for (int j = 0; j < 4; j++) {
        hh[j] = __float2bfloat16(vv[j]);
        ll[j] = __float2bfloat16(vv[j] - __bfloat162float(hh[j]));
    }
    ((uint2*)h)[i] = *(uint2*)hh;
    ((uint2*)l)[i] = *(uint2*)ll;
}

// WT[j][k] = split(W[k][j])
__global__ __launch_bounds__(256) void split_w(
    const float* __restrict__ W, __nv_bfloat16* __restrict__ th,
    __nv_bfloat16* __restrict__ tl)
{
    int j = blockIdx.x;
    int k = threadIdx.x;
    float x = W[k * DIM + j];
    __nv_bfloat16 h = __float2bfloat16(x);
    __nv_bfloat16 l = __float2bfloat16(x - __bfloat162float(h));
    th[j * DIM + k] = h;
    tl[j * DIM + k] = l;
}

// ---------------------------------------------------------------------------
// mma.sync GEMM: out[8192,256] = epi(A[8192,256] @ W)   (W given as WT hi/lo)
// CTA 64x64, K chunks of 64 in SMEM. 8 warps (2 m x 4 n), warp tile 32x16.
// D = Ah@Bh + Ah@Bl + Al@Bh, fp32 accumulate in registers.
// MODE 0: f32 + hi/lo out    MODE 1: hi/lo out (+extra)    MODE 2: f32 out
// ---------------------------------------------------------------------------
constexpr int LDT = 72;  // bf16 elems per SMEM row (64 + 8 pad)

template <int MODE>
__global__ __launch_bounds__(256) void gemm_mma(
    const __nv_bfloat16* __restrict__ Ah, const __nv_bfloat16* __restrict__ Al,
    const __nv_bfloat16* __restrict__ BTh, const __nv_bfloat16* __restrict__ BTl,
    const float* __restrict__ bias, const float* __restrict__ extra,
    const float* __restrict__ res, const float* __restrict__ scale_p,
    float* __restrict__ out_f32,
    __nv_bfloat16* __restrict__ out_h, __nv_bfloat16* __restrict__ out_l)
{
    __shared__ __align__(16) __nv_bfloat16 Ah_s[64 * LDT];
    __shared__ __align__(16) __nv_bfloat16 Al_s[64 * LDT];
    __shared__ __align__(16) __nv_bfloat16 Bh_s[64 * LDT];
    __shared__ __align__(16) __nv_bfloat16 Bl_s[64 * LDT];

    const int tid  = threadIdx.x;
    const int wid  = tid >> 5;
    const int lane = tid & 31;
    const int wm   = wid & 1;        // 2 warp rows (32 m each)
    const int wn   = wid >> 1;       // 4 warp cols (16 n each)
    const int m0   = blockIdx.y * 64;
    const int n0   = blockIdx.x * 64;

    const int lr = lane >> 2;        // 0..7
    const int lc = (lane & 3) * 2;   // 0,2,4,6

    float acc[2][2][4];
#pragma unroll
    for (int i = 0; i < 2; i++)
#pragma unroll
        for (int j = 0; j < 2; j++)
#pragma unroll
            for (int q = 0; q < 4; q++) acc[i][j][q] = 0.0f;

    for (int k0 = 0; k0 < DIM; k0 += 64) {
        // ---- stage chunk: A 64x64 hi/lo, B 64x64 hi/lo ----
#pragma unroll
        for (int it = 0; it < 2; it++) {
            const int v = tid + it * 256;         // 0..511
            const int row = v >> 3, cv = v & 7;
            const int so = row * LDT + cv * 8;
            const size_t ga = (size_t)(m0 + row) * DIM + k0 + cv * 8;
            const size_t gb = (size_t)(n0 + row) * DIM + k0 + cv * 8;
            *(uint4*)&Ah_s[so] = *(const uint4*)(Ah + ga);
            *(uint4*)&Al_s[so] = *(const uint4*)(Al + ga);
            *(uint4*)&Bh_s[so] = *(const uint4*)(BTh + gb);
            *(uint4*)&Bl_s[so] = *(const uint4*)(BTl + gb);
        }
        __syncthreads();

#pragma unroll
        for (int ks = 0; ks < 4; ks++) {
            const int kb = ks * 16;
            u32 ah[2][4], al[2][4], bh[2][2], bl[2][2];
#pragma unroll
            for (int mt = 0; mt < 2; mt++) {
                const int base = (wm * 32 + mt * 16 + lr) * LDT + kb + lc;
                ah[mt][0] = *(const u32*)&Ah_s[base];
                ah[mt][1] = *(const u32*)&Ah_s[base + 8 * LDT];
                ah[mt][2] = *(const u32*)&Ah_s[base + 8];
                ah[mt][3] = *(const u32*)&Ah_s[base + 8 * LDT + 8];
                al[mt][0] = *(const u32*)&Al_s[base];
                al[mt][1] = *(const u32*)&Al_s[base + 8 * LDT];
                al[mt][2] = *(const u32*)&Al_s[base + 8];
                al[mt][3] = *(const u32*)&Al_s[base + 8 * LDT + 8];
            }
#pragma unroll
            for (int nt = 0; nt < 2; nt++) {
                const int base = (wn * 16 + nt * 8 + lr) * LDT + kb + lc;
                bh[nt][0] = *(const u32*)&Bh_s[base];
                bh[nt][1] = *(const u32*)&Bh_s[base + 8];
                bl[nt][0] = *(const u32*)&Bl_s[base];
                bl[nt][1] = *(const u32*)&Bl_s[base + 8];
            }
#pragma unroll
            for (int mt = 0; mt < 2; mt++)
#pragma unroll
                for (int nt = 0; nt < 2; nt++) {
                    mma_bf16(acc[mt][nt], ah[mt][0], ah[mt][1], ah[mt][2], ah[mt][3],
                             bh[nt][0], bh[nt][1]);
                    mma_bf16(acc[mt][nt], ah[mt][0], ah[mt][1], ah[mt][2], ah[mt][3],
                             bl[nt][0], bl[nt][1]);
                    mma_bf16(acc[mt][nt], al[mt][0], al[mt][1], al[mt][2], al[mt][3],
                             bh[nt][0], bh[nt][1]);
                }
        }
        __syncthreads();
    }

    // ---- epilogue ----
    float sc = 1.0f;
    if (MODE == 2) sc = *scale_p;

#pragma unroll
    for (int mt = 0; mt < 2; mt++)
#pragma unroll
        for (int nt = 0; nt < 2; nt++) {
            const int col = n0 + wn * 16 + nt * 8 + lc;
            const float2 bv = *(const float2*)(bias + col);
#pragma unroll
            for (int half = 0; half < 2; half++) {
                const int row = m0 + wm * 32 + mt * 16 + lr + half * 8;
                const size_t off = (size_t)row * DIM + col;
                float w0 = acc[mt][nt][2 * half + 0] + bv.x;
                float w1 = acc[mt][nt][2 * half + 1] + bv.y;
                if (MODE == 1 && extra) {
                    float2 e = *(const float2*)(extra + off);
                    w0 += e.x; w1 += e.y;
                }
                float o0 = silu_f(w0), o1 = silu_f(w1);
                if (MODE == 2) {
                    float2 rv = *(const float2*)(res + off);
                    o0 = (o0 + rv.x) * sc;
                    o1 = (o1 + rv.y) * sc;
                }
                if (MODE != 1)
                    *(float2*)(out_f32 + off) = make_float2(o0, o1);
                if (MODE != 2) {
                    __nv_bfloat16 h0 = __float2bfloat16(o0);
                    __nv_bfloat16 h1 = __float2bfloat16(o1);
                    __nv_bfloat16 l0 = __float2bfloat16(o0 - __bfloat162float(h0));
                    __nv_bfloat16 l1 = __float2bfloat16(o1 - __bfloat162float(h1));
                    __nv_bfloat16 hp[2] = { h0, h1 }, lp[2] = { l0, l1 };
                    *(u32*)(out_h + off) = *(u32*)hp;
                    *(u32*)(out_l + off) = *(u32*)lp;
                }
            }
        }
}

// ---------------------------------------------------------------------------
// Pair kernel (R4): 8 electrons per block, 256 threads.
// ---------------------------------------------------------------------------
constexpr int NPB   = 8;
constexpr int PAIRS = NPB * NNB;   // 192

__global__ __launch_bounds__(256) void pair_kernel(
    const float* __restrict__ elec1,
    const float* __restrict__ r,
    const float* __restrict__ r_nb,
    const int*   __restrict__ s,
    const int*   __restrict__ s_nb,
    const float* __restrict__ hinit_nb,
    const float* __restrict__ ee_scales,
    const float* __restrict__ ee_kernel,
    const float* __restrict__ ee_bias,
    const float* __restrict__ Wf,
    const float* __restrict__ bf,
    const float* __restrict__ Wsame,
    const float* __restrict__ Wdiff,
    float* __restrict__ hinit_msg)
{
    __shared__ __align__(16) float beta_s[PAIRS][F1];
    __shared__ float maskf_s[PAIRS];
    __shared__ u64  wd2_s [8][DIM];
    __shared__ u64  wsd2_s[8][DIM];
    __shared__ float eek_s[4 * F0];
    __shared__ float eeb_s[F0];
    __shared__ float wf_s[(F0 + NENV) * F1];
    __shared__ float bfv_s[F1];
    __shared__ float scl_s[NENV];

    const int tid = threadIdx.x;
    const int n0  = blockIdx.x * NPB;

    for (int i = tid; i < 4 * F0; i += 256) eek_s[i] = ee_kernel[i];
    for (int i = tid; i < F0; i += 256)     eeb_s[i] = ee_bias[i];
    for (int i = tid; i < (F0 + NENV) * F1; i += 256) wf_s[i] = Wf[i];
    if (tid < F1)   bfv_s[tid] = bf[tid];
    if (tid < NENV) scl_s[tid] = ee_scales[tid];

#pragma unroll
    for (int i = 0; i < 8; i++) {
        float d0 = Wdiff[(2 * i + 0) * DIM + tid];
        float d1 = Wdiff[(2 * i + 1) * DIM + tid];
        float s0 = Wsame[(2 * i + 0) * DIM + tid] - d0;
        float s1 = Wsame[(2 * i + 1) * DIM + tid] - d1;
        wd2_s [i][tid] = pk2(d0, d1);
        wsd2_s[i][tid] = pk2(s0, s1);
    }
    __syncthreads();

    if (tid < PAIRS) {
        const int nl = tid / NNB;
        const int k  = tid % NNB;
        const int n  = n0 + nl;

        const float rx = r[n * 3 + 0];
        const float ry = r[n * 3 + 1];
        const float rz = r[n * 3 + 2];
        const float* rn = r_nb + (size_t)(n * NNB + k) * 3;
        const float dx = rn[0] - rx;
        const float dy = rn[1] - ry;
        const float dz = rn[2] - rz;
        const float dist = sqrtf(dx * dx + dy * dy + dz * dz + 1e-12f);

        float feats[4] = { dist, dx, dy, dz };
        float h[F0];
#pragma unroll
        for (int j = 0; j < F0; j++) {
            float t = eeb_s[j];
#pragma unroll
            for (int f = 0; f < 4; f++) t += feats[f] * eek_s[f * F0 + j];
            h[j] = silu_f(t);
        }
        float env[NENV];
#pragma unroll
        for (int e = 0; e < NENV; e++) {
            float q = __fdividef(dist, scl_s[e]);
            env[e] = __expf(-q * q);
        }
        const float xx  = dist * (1.0f / CUTOFF);
        const float cut = (dist < CUTOFF)
                        ? (1.0f - xx) * (1.0f - xx) * (1.0f + 2.0f * xx)
                        : 0.0f;
#pragma unroll
        for (int i = 0; i < F1; i++) {
            float b = bfv_s[i];
#pragma unroll
            for (int j = 0; j < F0; j++)   b += h[j]   * wf_s[j * F1 + i];
#pragma unroll
            for (int e = 0; e < NENV; e++) b += env[e] * wf_s[(F0 + e) * F1 + i];
            beta_s[tid][i] = b * cut;
        }
        maskf_s[tid] = (s[n] == s_nb[n * NNB + k]) ? 1.0f : 0.0f;
    }
    __syncthreads();

    const int d = tid;
    for (int nl = 0; nl < NPB; nl++) {
        const int n = n0 + nl;
        const float e1 = elec1[(size_t)n * DIM + d];
        const float* hb = hinit_nb + ((size_t)n * NNB) * DIM + d;

        float uu[NNB];
#pragma unroll
        for (int k = 0; k < NNB; k++) uu[k] = e1 + hb[(size_t)k * DIM];
#pragma unroll
        for (int k = 0; k < NNB; k++) uu[k] = silu_f(uu[k]);

        u64 vall[8], vsm[8];
#pragma unroll
        for (int i = 0; i < 8; i++) { vall[i] = 0ull; vsm[i] = 0ull; }

#pragma unroll
        for (int k = 0; k < NNB; k++) {
            const int pair = nl * NNB + k;
            const float u  = uu[k];
            const float um = u * maskf_s[pair];
            const u64 u2   = pk2(u, u);
            const u64 um2  = pk2(um, um);
            const u64* bp  = (const u64*)beta_s[pair];
#pragma unroll
            for (int i = 0; i < 8; i++) {
                vall[i] = f2fma(u2,  bp[i], vall[i]);
                vsm[i]  = f2fma(um2, bp[i], vsm[i]);
            }
        }

        u64 r2 = 0ull;
#pragma unroll
        for (int i = 0; i < 8; i++) r2 = f2fma(wd2_s[i][d],  vall[i], r2);
#pragma unroll
        for (int i = 0; i < 8; i++) r2 = f2fma(wsd2_s[i][d], vsm[i],  r2);
        float2 rr = upk2(r2);
        hinit_msg[(size_t)n * DIM + d] = rr.x + rr.y;
    }
}

// ---------------------------------------------------------------------------
extern "C" void kernel_launch(void* const* d_in, const int* in_sizes, int n_in,
                              void* d_out, int out_size)
{
    const float* elec     = (const float*)d_in[0];
    const float* msg      = (const float*)d_in[1];
    const float* r        = (const float*)d_in[2];
    const float* r_nb     = (const float*)d_in[3];
    const int*   s        = (const int*)  d_in[4];
    const int*   s_nb     = (const int*)  d_in[5];
    const float* hinit_nb = (const float*)d_in[6];
    const float* W_in     = (const float*)d_in[7];
    const float* b_in     = (const float*)d_in[8];
    const float* ee_scales= (const float*)d_in[9];
    const float* ee_kernel= (const float*)d_in[10];
    const float* ee_bias  = (const float*)d_in[11];
    const float* Wf       = (const float*)d_in[12];
    const float* bf       = (const float*)d_in[13];
    const float* Wsame    = (const float*)d_in[14];
    const float* Wdiff    = (const float*)d_in[15];
    const float* W1       = (const float*)d_in[16];
    const float* b1       = (const float*)d_in[17];
    const float* W2       = (const float*)d_in[18];
    const float* b2       = (const float*)d_in[19];
    const float* W3       = (const float*)d_in[20];
    const float* b3       = (const float*)d_in[21];
    const float* scale    = (const float*)d_in[22];

    float* out = (float*)d_out;

    float *e1, *hmsg;
    __nv_bfloat16 *eh, *el, *e1h, *e1l, *t1h, *t1l, *t2h, *t2l;
    __nv_bfloat16 *w0h, *w0l, *w1h, *w1l, *w2h, *w2l, *w3h, *w3l;
    cudaGetSymbolAddress((void**)&e1,   g_e1);
    cudaGetSymbolAddress((void**)&hmsg, g_hmsg);
    cudaGetSymbolAddress((void**)&eh,  g_eh);  cudaGetSymbolAddress((void**)&el,  g_el);
    cudaGetSymbolAddress((void**)&e1h, g_e1h); cudaGetSymbolAddress((void**)&e1l, g_e1l);
    cudaGetSymbolAddress((void**)&t1h, g_t1h); cudaGetSymbolAddress((void**)&t1l, g_t1l);
    cudaGetSymbolAddress((void**)&t2h, g_t2h); cudaGetSymbolAddress((void**)&t2l, g_t2l);
    cudaGetSymbolAddress((void**)&w0h, g_w0h); cudaGetSymbolAddress((void**)&w0l, g_w0l);
    cudaGetSymbolAddress((void**)&w1h, g_w1h); cudaGetSymbolAddress((void**)&w1l, g_w1l);
    cudaGetSymbolAddress((void**)&w2h, g_w2h); cudaGetSymbolAddress((void**)&w2l, g_w2l);
    cudaGetSymbolAddress((void**)&w3h, g_w3h); cudaGetSymbolAddress((void**)&w3l, g_w3l);

    // prep: split elec + transpose-split weights
    split_f32<<<(N_ELEC * DIM / 4 + 255) / 256, 256>>>(elec, eh, el, N_ELEC * DIM / 4);
    split_w<<<DIM, DIM>>>(W_in, w0h, w0l);
    split_w<<<DIM, DIM>>>(W1,   w1h, w1l);
    split_w<<<DIM, DIM>>>(W2,   w2h, w2l);
    split_w<<<DIM, DIM>>>(W3,   w3h, w3l);

    dim3 ggrid(DIM / 64, N_ELEC / 64);   // (4, 128) = 512 CTAs

    // elec1 = silu(elec @ W_in + b_in): f32 + hi/lo
    gemm_mma<0><<<ggrid, 256>>>(eh, el, w0h, w0l, b_in,
                                nullptr, nullptr, nullptr, e1, e1h, e1l);

    pair_kernel<<<N_ELEC / NPB, 256>>>(e1, r, r_nb, s, s_nb, hinit_nb,
                                       ee_scales, ee_kernel, ee_bias, Wf, bf,
                                       Wsame, Wdiff, hmsg);

    // t1 = silu(elec1 @ W1 + b1 + hmsg): hi/lo only
    gemm_mma<1><<<ggrid, 256>>>(e1h, e1l, w1h, w1l, b1,
                                hmsg, nullptr, nullptr, nullptr, t1h, t1l);
    // t2 = silu(t1 @ W2 + b2 + msg): hi/lo only
    gemm_mma<1><<<ggrid, 256>>>(t1h, t1l, w2h, w2l, b2,
                                msg, nullptr, nullptr, nullptr, t2h, t2l);
    // out = (silu(t2 @ W3 + b3) + elec1) * scale: f32 only
    gemm_mma<2><<<ggrid, 256>>>(t2h, t2l, w3h, w3l, b3,
                                nullptr, e1, scale, out, nullptr, nullptr);
}

// round 8
// speedup vs baseline: 1.6526x; 1.0485x over previous
#include <cuda_runtime.h>
#include <cuda_bf16.h>
#include <cstdint>

typedef unsigned long long u64;
typedef unsigned int u32;
typedef __nv_bfloat16 bf16;

constexpr int N_ELEC = 8192;
constexpr int DIM    = 256;
constexpr int NNB    = 24;
constexpr int F0     = 32;
constexpr int F1     = 16;
constexpr int NENV   = 8;
constexpr float CUTOFF = 5.0f;

// ---------------- scratch (device globals; no allocation) ----------------
__device__ float g_e1  [N_ELEC * DIM];
__device__ float g_hmsg[N_ELEC * DIM];
__device__ bf16 g_e1h[N_ELEC * DIM], g_e1l[N_ELEC * DIM];
__device__ bf16 g_t1h[N_ELEC * DIM], g_t1l[N_ELEC * DIM];
__device__ bf16 g_t2h[N_ELEC * DIM], g_t2l[N_ELEC * DIM];
__device__ bf16 g_w0h[DIM * DIM], g_w0l[DIM * DIM];
__device__ bf16 g_w1h[DIM * DIM], g_w1l[DIM * DIM];
__device__ bf16 g_w2h[DIM * DIM], g_w2l[DIM * DIM];
__device__ bf16 g_w3h[DIM * DIM], g_w3l[DIM * DIM];

// ---------------- helpers ----------------
__device__ __forceinline__ u64 pk2(float x, float y) {
    u64 r; asm("mov.b64 %0, {%1,%2};" : "=l"(r) : "f"(x), "f"(y)); return r;
}
__device__ __forceinline__ float2 upk2(u64 v) {
    float2 f; asm("mov.b64 {%0,%1}, %2;" : "=f"(f.x), "=f"(f.y) : "l"(v)); return f;
}
__device__ __forceinline__ u64 f2fma(u64 a, u64 b, u64 c) {
    u64 d; asm("fma.rn.f32x2 %0, %1, %2, %3;" : "=l"(d) : "l"(a), "l"(b), "l"(c));
    return d;
}
__device__ __forceinline__ float silu_f(float x) {
    float e = __expf(-x);
    return __fdividef(x, 1.0f + e);
}

__device__ __forceinline__ void mma_bf16(
    float c[4], u32 a0, u32 a1, u32 a2, u32 a3, u32 b0, u32 b1)
{
    asm volatile(
        "mma.sync.aligned.m16n8k16.row.col.f32.bf16.bf16.f32 "
        "{%0,%1,%2,%3}, {%4,%5,%6,%7}, {%8,%9}, {%0,%1,%2,%3};"
        : "+f"(c[0]), "+f"(c[1]), "+f"(c[2]), "+f"(c[3])
        : "r"(a0), "r"(a1), "r"(a2), "r"(a3), "r"(b0), "r"(b1));
}

__device__ __forceinline__ void ldm_x4(u32 r[4], u32 addr) {
    asm volatile(
        "ldmatrix.sync.aligned.m8n8.x4.shared.b16 {%0,%1,%2,%3}, [%4];"
        : "=r"(r[0]), "=r"(r[1]), "=r"(r[2]), "=r"(r[3]) : "r"(addr));
}

// ---------------- prep: merged transpose-split of 4 weight matrices ----------
// th[j*DIM+k] = hi(W[k*DIM+j]), tl = residual.
__global__ __launch_bounds__(256) void split_weights(
    const float* __restrict__ W0, const float* __restrict__ W1,
    const float* __restrict__ W2, const float* __restrict__ W3,
    bf16* __restrict__ o0h, bf16* __restrict__ o0l,
    bf16* __restrict__ o1h, bf16* __restrict__ o1l,
    bf16* __restrict__ o2h, bf16* __restrict__ o2l,
    bf16* __restrict__ o3h, bf16* __restrict__ o3l)
{
    __shared__ float t[32][33];
    const int z = blockIdx.z;
    const float* W = (z == 0) ? W0 : (z == 1) ? W1 : (z == 2) ? W2 : W3;
    bf16* oh = (z == 0) ? o0h : (z == 1) ? o1h : (z == 2) ? o2h : o3h;
    bf16* ol = (z == 0) ? o0l : (z == 1) ? o1l : (z == 2) ? o2l : o3l;

    const int tx = threadIdx.x;          // 0..31
    const int ty = threadIdx.y;          // 0..7
    const int jb = blockIdx.x * 32;      // output row block (j)
    const int kb = blockIdx.y * 32;      // output col block (k)

    // load W[kb + r][jb + tx], r = ty + i*8  (coalesced)
#pragma unroll
    for (int i = 0; i < 4; i++)
        t[ty + i * 8][tx] = W[(size_t)(kb + ty + i * 8) * DIM + jb + tx];
    __syncthreads();

    // write oh[(jb + r2)*DIM + kb + tx] = split(t[tx][r2]), r2 = ty + i*8
#pragma unroll
    for (int i = 0; i < 4; i++) {
        const float v = t[tx][ty + i * 8];
        const bf16 h = __float2bfloat16(v);
        const bf16 l = __float2bfloat16(v - __bfloat162float(h));
        const size_t o = (size_t)(jb + ty + i * 8) * DIM + kb + tx;
        oh[o] = h;
        ol[o] = l;
    }
}

// ---------------------------------------------------------------------------
// mma.sync GEMM: out[8192,256] = epi(A[8192,256] @ W)  (W given as WT hi/lo)
// CTA 64x64, K chunks of 64 double-buffered in SMEM, ldmatrix fragments.
// D = Ah@Bh + Ah@Bl + Al@Bh (fp32 regs).
// MODE 0: A is f32 (split during staging); f32 + hi/lo out
// MODE 1: hi/lo A; hi/lo out (+extra)
// MODE 2: hi/lo A; f32 out = (silu(acc+bias)+res)*scale
// ---------------------------------------------------------------------------
constexpr int LDT = 72;                      // bf16 per SMEM row (64 + 8 pad)
constexpr int ARR = 64 * LDT;                // elems per array (4608)
constexpr int BUF = 4 * ARR;                 // elems per buffer (18432)
constexpr int GSMEM = 2 * BUF * 2;           // bytes (73728)

template <int MODE>
__global__ __launch_bounds__(256) void gemm_mma(
    const float* __restrict__ A32,
    const bf16* __restrict__ Ah, const bf16* __restrict__ Al,
    const bf16* __restrict__ BTh, const bf16* __restrict__ BTl,
    const float* __restrict__ bias, const float* __restrict__ extra,
    const float* __restrict__ res, const float* __restrict__ scale_p,
    float* __restrict__ out_f32,
    bf16* __restrict__ out_h, bf16* __restrict__ out_l)
{
    extern __shared__ bf16 sm[];
    const u32 smb = (u32)__cvta_generic_to_shared(sm);

    const int tid  = threadIdx.x;
    const int wid  = tid >> 5;
    const int lane = tid & 31;
    const int wm   = wid & 1;
    const int wn   = wid >> 1;
    const int m0   = blockIdx.y * 64;
    const int n0   = blockIdx.x * 64;

    const int lr = lane >> 2;
    const int lc = (lane & 3) * 2;

    // staging slots: slot s -> row r = s>>3, kvec kv = s&7 (8 bf16 each)
    const int s0r = tid >> 3, s0v = tid & 7;
    const int s1r = (tid + 256) >> 3, s1v = tid & 7;   // (tid+256)&7 == tid&7

    float4 pa32[4];          // MODE 0: 2 slots x 2 float4
    uint4  pah[2], pal[2];   // bf16 modes
    uint4  pbh[2], pbl[2];

    // ---- prefetch chunk 0 ----
    {
        const int k0 = 0;
        if (MODE == 0) {
            pa32[0] = *(const float4*)(A32 + (size_t)(m0 + s0r) * DIM + k0 + s0v * 8);
            pa32[1] = *(const float4*)(A32 + (size_t)(m0 + s0r) * DIM + k0 + s0v * 8 + 4);
            pa32[2] = *(const float4*)(A32 + (size_t)(m0 + s1r) * DIM + k0 + s1v * 8);
            pa32[3] = *(const float4*)(A32 + (size_t)(m0 + s1r) * DIM + k0 + s1v * 8 + 4);
        } else {
            pah[0] = *(const uint4*)(Ah + (size_t)(m0 + s0r) * DIM + k0 + s0v * 8);
            pal[0] = *(const uint4*)(Al + (size_t)(m0 + s0r) * DIM + k0 + s0v * 8);
            pah[1] = *(const uint4*)(Ah + (size_t)(m0 + s1r) * DIM + k0 + s1v * 8);
            pal[1] = *(const uint4*)(Al + (size_t)(m0 + s1r) * DIM + k0 + s1v * 8);
        }
        pbh[0] = *(const uint4*)(BTh + (size_t)(n0 + s0r) * DIM + k0 + s0v * 8);
        pbl[0] = *(const uint4*)(BTl + (size_t)(n0 + s0r) * DIM + k0 + s0v * 8);
        pbh[1] = *(const uint4*)(BTh + (size_t)(n0 + s1r) * DIM + k0 + s1v * 8);
        pbl[1] = *(const uint4*)(BTl + (size_t)(n0 + s1r) * DIM + k0 + s1v * 8);
    }

    float acc[2][2][4];
#pragma unroll
    for (int i = 0; i < 2; i++)
#pragma unroll
        for (int j = 0; j < 2; j++)
#pragma unroll
            for (int q = 0; q < 4; q++) acc[i][j][q] = 0.0f;

    // precomputed ldmatrix lane addresses (element offsets within an array)
    const int a_row = wm * 32 + ((lane >> 3) & 1) * 8 + (lane & 7);
    const int a_kof = (lane >> 4) << 3;
    const int b_row = wn * 16 + ((lane >> 4) << 3) + (lane & 7);
    const int b_kof = ((lane >> 3) & 1) << 3;

    auto store_chunk = [&](int buf) {
        bf16* AhS = sm + buf * BUF;
        bf16* AlS = AhS + ARR;
        bf16* BhS = AhS + 2 * ARR;
        bf16* BlS = AhS + 3 * ARR;
        if (MODE == 0) {
            bf16 h[8], l[8];
            float v[8] = { pa32[0].x, pa32[0].y, pa32[0].z, pa32[0].w,
                           pa32[1].x, pa32[1].y, pa32[1].z, pa32[1].w };
#pragma unroll
            for (int j = 0; j < 8; j++) {
                h[j] = __float2bfloat16(v[j]);
                l[j] = __float2bfloat16(v[j] - __bfloat162float(h[j]));
            }
            *(uint4*)&AhS[s0r * LDT + s0v * 8] = *(uint4*)h;
            *(uint4*)&AlS[s0r * LDT + s0v * 8] = *(uint4*)l;
            float v2[8] = { pa32[2].x, pa32[2].y, pa32[2].z, pa32[2].w,
                            pa32[3].x, pa32[3].y, pa32[3].z, pa32[3].w };
#pragma unroll
            for (int j = 0; j < 8; j++) {
                h[j] = __float2bfloat16(v2[j]);
                l[j] = __float2bfloat16(v2[j] - __bfloat162float(h[j]));
            }
            *(uint4*)&AhS[s1r * LDT + s1v * 8] = *(uint4*)h;
            *(uint4*)&AlS[s1r * LDT + s1v * 8] = *(uint4*)l;
        } else {
            *(uint4*)&AhS[s0r * LDT + s0v * 8] = pah[0];
            *(uint4*)&AlS[s0r * LDT + s0v * 8] = pal[0];
            *(uint4*)&AhS[s1r * LDT + s1v * 8] = pah[1];
            *(uint4*)&AlS[s1r * LDT + s1v * 8] = pal[1];
        }
        *(uint4*)&BhS[s0r * LDT + s0v * 8] = pbh[0];
        *(uint4*)&BlS[s0r * LDT + s0v * 8] = pbl[0];
        *(uint4*)&BhS[s1r * LDT + s1v * 8] = pbh[1];
        *(uint4*)&BlS[s1r * LDT + s1v * 8] = pbl[1];
    };

    store_chunk(0);
    __syncthreads();

    for (int c = 0; c < 4; c++) {
        const int buf = c & 1;
        if (c < 3) {
            const int k0 = (c + 1) * 64;
            if (MODE == 0) {
                pa32[0] = *(const float4*)(A32 + (size_t)(m0 + s0r) * DIM + k0 + s0v * 8);
                pa32[1] = *(const float4*)(A32 + (size_t)(m0 + s0r) * DIM + k0 + s0v * 8 + 4);
                pa32[2] = *(const float4*)(A32 + (size_t)(m0 + s1r) * DIM + k0 + s1v * 8);
                pa32[3] = *(const float4*)(A32 + (size_t)(m0 + s1r) * DIM + k0 + s1v * 8 + 4);
            } else {
                pah[0] = *(const uint4*)(Ah + (size_t)(m0 + s0r) * DIM + k0 + s0v * 8);
                pal[0] = *(const uint4*)(Al + (size_t)(m0 + s0r) * DIM + k0 + s0v * 8);
                pah[1] = *(const uint4*)(Ah + (size_t)(m0 + s1r) * DIM + k0 + s1v * 8);
                pal[1] = *(const uint4*)(Al + (size_t)(m0 + s1r) * DIM + k0 + s1v * 8);
            }
            pbh[0] = *(const uint4*)(BTh + (size_t)(n0 + s0r) * DIM + k0 + s0v * 8);
            pbl[0] = *(const uint4*)(BTl + (size_t)(n0 + s0r) * DIM + k0 + s0v * 8);
            pbh[1] = *(const uint4*)(BTh + (size_t)(n0 + s1r) * DIM + k0 + s1v * 8);
            pbl[1] = *(const uint4*)(BTl + (size_t)(n0 + s1r) * DIM + k0 + s1v * 8);
        }

        const u32 ah_b = smb + (buf * BUF) * 2;
        const u32 al_b = ah_b + ARR * 2;
        const u32 bh_b = ah_b + 2 * ARR * 2;
        const u32 bl_b = ah_b + 3 * ARR * 2;

#pragma unroll
        for (int ks = 0; ks < 4; ks++) {
            const int kb = ks * 16;
            u32 ah[2][4], al[2][4], bh[4], bl[4];
#pragma unroll
            for (int mt = 0; mt < 2; mt++) {
                const u32 aoff = (u32)((a_row + mt * 16) * LDT + kb + a_kof) * 2;
                ldm_x4(ah[mt], ah_b + aoff);
                ldm_x4(al[mt], al_b + aoff);
            }
            const u32 boff = (u32)(b_row * LDT + kb + b_kof) * 2;
            ldm_x4(bh, bh_b + boff);
            ldm_x4(bl, bl_b + boff);

#pragma unroll
            for (int mt = 0; mt < 2; mt++)
#pragma unroll
                for (int nt = 0; nt < 2; nt++) {
                    mma_bf16(acc[mt][nt], ah[mt][0], ah[mt][1], ah[mt][2], ah[mt][3],
                             bh[nt * 2], bh[nt * 2 + 1]);
                    mma_bf16(acc[mt][nt], ah[mt][0], ah[mt][1], ah[mt][2], ah[mt][3],
                             bl[nt * 2], bl[nt * 2 + 1]);
                    mma_bf16(acc[mt][nt], al[mt][0], al[mt][1], al[mt][2], al[mt][3],
                             bh[nt * 2], bh[nt * 2 + 1]);
                }
        }

        if (c < 3) store_chunk(buf ^ 1);
        __syncthreads();
    }

    // ---- epilogue ----
    float sc = 1.0f;
    if (MODE == 2) sc = *scale_p;

#pragma unroll
    for (int mt = 0; mt < 2; mt++)
#pragma unroll
        for (int nt = 0; nt < 2; nt++) {
            const int col = n0 + wn * 16 + nt * 8 + lc;
            const float2 bv = *(const float2*)(bias + col);
#pragma unroll
            for (int half = 0; half < 2; half++) {
                const int row = m0 + wm * 32 + mt * 16 + lr + half * 8;
                const size_t off = (size_t)row * DIM + col;
                float w0 = acc[mt][nt][2 * half + 0] + bv.x;
                float w1 = acc[mt][nt][2 * half + 1] + bv.y;
                if (MODE == 1) {
                    float2 e = *(const float2*)(extra + off);
                    w0 += e.x; w1 += e.y;
                }
                float o0 = silu_f(w0), o1 = silu_f(w1);
                if (MODE == 2) {
                    float2 rv = *(const float2*)(res + off);
                    o0 = (o0 + rv.x) * sc;
                    o1 = (o1 + rv.y) * sc;
                }
                if (MODE != 1)
                    *(float2*)(out_f32 + off) = make_float2(o0, o1);
                if (MODE != 2) {
                    bf16 h0 = __float2bfloat16(o0);
                    bf16 h1 = __float2bfloat16(o1);
                    bf16 l0 = __float2bfloat16(o0 - __bfloat162float(h0));
                    bf16 l1 = __float2bfloat16(o1 - __bfloat162float(h1));
                    bf16 hp[2] = { h0, h1 }, lp[2] = { l0, l1 };
                    *(u32*)(out_h + off) = *(u32*)hp;
                    *(u32*)(out_l + off) = *(u32*)lp;
                }
            }
        }
}

// ---------------------------------------------------------------------------
// Pair kernel (R4): 8 electrons per block, 256 threads.
// ---------------------------------------------------------------------------
constexpr int NPB   = 8;
constexpr int PAIRS = NPB * NNB;   // 192

__global__ __launch_bounds__(256) void pair_kernel(
    const float* __restrict__ elec1,
    const float* __restrict__ r,
    const float* __restrict__ r_nb,
    const int*   __restrict__ s,
    const int*   __restrict__ s_nb,
    const float* __restrict__ hinit_nb,
    const float* __restrict__ ee_scales,
    const float* __restrict__ ee_kernel,
    const float* __restrict__ ee_bias,
    const float* __restrict__ Wf,
    const float* __restrict__ bf,
    const float* __restrict__ Wsame,
    const float* __restrict__ Wdiff,
    float* __restrict__ hinit_msg)
{
    __shared__ __align__(16) float beta_s[PAIRS][F1];
    __shared__ float maskf_s[PAIRS];
    __shared__ u64  wd2_s [8][DIM];
    __shared__ u64  wsd2_s[8][DIM];
    __shared__ float eek_s[4 * F0];
    __shared__ float eeb_s[F0];
    __shared__ float wf_s[(F0 + NENV) * F1];
    __shared__ float bfv_s[F1];
    __shared__ float scl_s[NENV];

    const int tid = threadIdx.x;
    const int n0  = blockIdx.x * NPB;

    for (int i = tid; i < 4 * F0; i += 256) eek_s[i] = ee_kernel[i];
    for (int i = tid; i < F0; i += 256)     eeb_s[i] = ee_bias[i];
    for (int i = tid; i < (F0 + NENV) * F1; i += 256) wf_s[i] = Wf[i];
    if (tid < F1)   bfv_s[tid] = bf[tid];
    if (tid < NENV) scl_s[tid] = ee_scales[tid];

#pragma unroll
    for (int i = 0; i < 8; i++) {
        float d0 = Wdiff[(2 * i + 0) * DIM + tid];
        float d1 = Wdiff[(2 * i + 1) * DIM + tid];
        float s0 = Wsame[(2 * i + 0) * DIM + tid] - d0;
        float s1 = Wsame[(2 * i + 1) * DIM + tid] - d1;
        wd2_s [i][tid] = pk2(d0, d1);
        wsd2_s[i][tid] = pk2(s0, s1);
    }
    __syncthreads();

    if (tid < PAIRS) {
        const int nl = tid / NNB;
        const int k  = tid % NNB;
        const int n  = n0 + nl;

        const float rx = r[n * 3 + 0];
        const float ry = r[n * 3 + 1];
        const float rz = r[n * 3 + 2];
        const float* rn = r_nb + (size_t)(n * NNB + k) * 3;
        const float dx = rn[0] - rx;
        const float dy = rn[1] - ry;
        const float dz = rn[2] - rz;
        const float dist = sqrtf(dx * dx + dy * dy + dz * dz + 1e-12f);

        float feats[4] = { dist, dx, dy, dz };
        float h[F0];
#pragma unroll
        for (int j = 0; j < F0; j++) {
            float t = eeb_s[j];
#pragma unroll
            for (int f = 0; f < 4; f++) t += feats[f] * eek_s[f * F0 + j];
            h[j] = silu_f(t);
        }
        float env[NENV];
#pragma unroll
        for (int e = 0; e < NENV; e++) {
            float q = __fdividef(dist, scl_s[e]);
            env[e] = __expf(-q * q);
        }
        const float xx  = dist * (1.0f / CUTOFF);
        const float cut = (dist < CUTOFF)
                        ? (1.0f - xx) * (1.0f - xx) * (1.0f + 2.0f * xx)
                        : 0.0f;
#pragma unroll
        for (int i = 0; i < F1; i++) {
            float b = bfv_s[i];
#pragma unroll
            for (int j = 0; j < F0; j++)   b += h[j]   * wf_s[j * F1 + i];
#pragma unroll
            for (int e = 0; e < NENV; e++) b += env[e] * wf_s[(F0 + e) * F1 + i];
            beta_s[tid][i] = b * cut;
        }
        maskf_s[tid] = (s[n] == s_nb[n * NNB + k]) ? 1.0f : 0.0f;
    }
    __syncthreads();

    const int d = tid;
    for (int nl = 0; nl < NPB; nl++) {
        const int n = n0 + nl;
        const float e1 = elec1[(size_t)n * DIM + d];
        const float* hb = hinit_nb + ((size_t)n * NNB) * DIM + d;

        float uu[NNB];
#pragma unroll
        for (int k = 0; k < NNB; k++) uu[k] = e1 + hb[(size_t)k * DIM];
#pragma unroll
        for (int k = 0; k < NNB; k++) uu[k] = silu_f(uu[k]);

        u64 vall[8], vsm[8];
#pragma unroll
        for (int i = 0; i < 8; i++) { vall[i] = 0ull; vsm[i] = 0ull; }

#pragma unroll
        for (int k = 0; k < NNB; k++) {
            const int pair = nl * NNB + k;
            const float u  = uu[k];
            const float um = u * maskf_s[pair];
            const u64 u2   = pk2(u, u);
            const u64 um2  = pk2(um, um);
            const u64* bp  = (const u64*)beta_s[pair];
#pragma unroll
            for (int i = 0; i < 8; i++) {
                vall[i] = f2fma(u2,  bp[i], vall[i]);
                vsm[i]  = f2fma(um2, bp[i], vsm[i]);
            }
        }

        u64 r2 = 0ull;
#pragma unroll
        for (int i = 0; i < 8; i++) r2 = f2fma(wd2_s[i][d],  vall[i], r2);
#pragma unroll
        for (int i = 0; i < 8; i++) r2 = f2fma(wsd2_s[i][d], vsm[i],  r2);
        float2 rr = upk2(r2);
        hinit_msg[(size_t)n * DIM + d] = rr.x + rr.y;
    }
}

// ---------------------------------------------------------------------------
extern "C" void kernel_launch(void* const* d_in, const int* in_sizes, int n_in,
                              void* d_out, int out_size)
{
    const float* elec     = (const float*)d_in[0];
    const float* msg      = (const float*)d_in[1];
    const float* r        = (const float*)d_in[2];
    const float* r_nb     = (const float*)d_in[3];
    const int*   s        = (const int*)  d_in[4];
    const int*   s_nb     = (const int*)  d_in[5];
    const float* hinit_nb = (const float*)d_in[6];
    const float* W_in     = (const float*)d_in[7];
    const float* b_in     = (const float*)d_in[8];
    const float* ee_scales= (const float*)d_in[9];
    const float* ee_kernel= (const float*)d_in[10];
    const float* ee_bias  = (const float*)d_in[11];
    const float* Wf       = (const float*)d_in[12];
    const float* bf       = (const float*)d_in[13];
    const float* Wsame    = (const float*)d_in[14];
    const float* Wdiff    = (const float*)d_in[15];
    const float* W1       = (const float*)d_in[16];
    const float* b1       = (const float*)d_in[17];
    const float* W2       = (const float*)d_in[18];
    const float* b2       = (const float*)d_in[19];
    const float* W3       = (const float*)d_in[20];
    const float* b3       = (const float*)d_in[21];
    const float* scale    = (const float*)d_in[22];

    float* out = (float*)d_out;

    float *e1, *hmsg;
    bf16 *e1h, *e1l, *t1h, *t1l, *t2h, *t2l;
    bf16 *w0h, *w0l, *w1h, *w1l, *w2h, *w2l, *w3h, *w3l;
    cudaGetSymbolAddress((void**)&e1,   g_e1);
    cudaGetSymbolAddress((void**)&hmsg, g_hmsg);
    cudaGetSymbolAddress((void**)&e1h, g_e1h); cudaGetSymbolAddress((void**)&e1l, g_e1l);
    cudaGetSymbolAddress((void**)&t1h, g_t1h); cudaGetSymbolAddress((void**)&t1l, g_t1l);
    cudaGetSymbolAddress((void**)&t2h, g_t2h); cudaGetSymbolAddress((void**)&t2l, g_t2l);
    cudaGetSymbolAddress((void**)&w0h, g_w0h); cudaGetSymbolAddress((void**)&w0l, g_w0l);
    cudaGetSymbolAddress((void**)&w1h, g_w1h); cudaGetSymbolAddress((void**)&w1l, g_w1l);
    cudaGetSymbolAddress((void**)&w2h, g_w2h); cudaGetSymbolAddress((void**)&w2l, g_w2l);
    cudaGetSymbolAddress((void**)&w3h, g_w3h); cudaGetSymbolAddress((void**)&w3l, g_w3l);

    cudaFuncSetAttribute(gemm_mma<0>, cudaFuncAttributeMaxDynamicSharedMemorySize, GSMEM);
    cudaFuncSetAttribute(gemm_mma<1>, cudaFuncAttributeMaxDynamicSharedMemorySize, GSMEM);
    cudaFuncSetAttribute(gemm_mma<2>, cudaFuncAttributeMaxDynamicSharedMemorySize, GSMEM);

    // prep: transpose-split all 4 weights in one kernel
    split_weights<<<dim3(8, 8, 4), dim3(32, 8)>>>(
        W_in, W1, W2, W3, w0h, w0l, w1h, w1l, w2h, w2l, w3h, w3l);

    dim3 ggrid(DIM / 64, N_ELEC / 64);   // (4, 128) = 512 CTAs

    // elec1 = silu(elec @ W_in + b_in): f32 A in, f32 + hi/lo out
    gemm_mma<0><<<ggrid, 256, GSMEM>>>(elec, nullptr, nullptr, w0h, w0l, b_in,
                                       nullptr, nullptr, nullptr, e1, e1h, e1l);

    pair_kernel<<<N_ELEC / NPB, 256>>>(e1, r, r_nb, s, s_nb, hinit_nb,
                                       ee_scales, ee_kernel, ee_bias, Wf, bf,
                                       Wsame, Wdiff, hmsg);

    // t1 = silu(elec1 @ W1 + b1 + hmsg): hi/lo out
    gemm_mma<1><<<ggrid, 256, GSMEM>>>(nullptr, e1h, e1l, w1h, w1l, b1,
                                       hmsg, nullptr, nullptr, nullptr, t1h, t1l);
    // t2 = silu(t1 @ W2 + b2 + msg): hi/lo out
    gemm_mma<1><<<ggrid, 256, GSMEM>>>(nullptr, t1h, t1l, w2h, w2l, b2,
                                       msg, nullptr, nullptr, nullptr, t2h, t2l);
    // out = (silu(t2 @ W3 + b3) + elec1) * scale: f32 out
    gemm_mma<2><<<ggrid, 256, GSMEM>>>(nullptr, t2h, t2l, w3h, w3l, b3,
                                       nullptr, e1, scale, out, nullptr, nullptr);
}

// round 9
// speedup vs baseline: 1.8612x; 1.1262x over previous
#include <cuda_runtime.h>
#include <cuda_bf16.h>
#include <cstdint>

typedef unsigned long long u64;
typedef unsigned int u32;
typedef __nv_bfloat16 bf16;

constexpr int N_ELEC = 8192;
constexpr int DIM    = 256;
constexpr int NNB    = 24;
constexpr int F0     = 32;
constexpr int F1     = 16;
constexpr int NENV   = 8;
constexpr float CUTOFF = 5.0f;

// ---------------- scratch (device globals; no allocation) ----------------
__device__ float g_e1  [N_ELEC * DIM];
__device__ float g_hmsg[N_ELEC * DIM];
__device__ bf16 g_e1h[N_ELEC * DIM], g_e1l[N_ELEC * DIM];
__device__ bf16 g_t1h[N_ELEC * DIM], g_t1l[N_ELEC * DIM];
__device__ bf16 g_t2h[N_ELEC * DIM], g_t2l[N_ELEC * DIM];
__device__ bf16 g_w0h[DIM * DIM], g_w0l[DIM * DIM];
__device__ bf16 g_w1h[DIM * DIM], g_w1l[DIM * DIM];
__device__ bf16 g_w2h[DIM * DIM], g_w2l[DIM * DIM];
__device__ bf16 g_w3h[DIM * DIM], g_w3l[DIM * DIM];

// ---------------- helpers ----------------
__device__ __forceinline__ u64 pk2(float x, float y) {
    u64 r; asm("mov.b64 %0, {%1,%2};" : "=l"(r) : "f"(x), "f"(y)); return r;
}
__device__ __forceinline__ float2 upk2(u64 v) {
    float2 f; asm("mov.b64 {%0,%1}, %2;" : "=f"(f.x), "=f"(f.y) : "l"(v)); return f;
}
__device__ __forceinline__ u64 f2fma(u64 a, u64 b, u64 c) {
    u64 d; asm("fma.rn.f32x2 %0, %1, %2, %3;" : "=l"(d) : "l"(a), "l"(b), "l"(c));
    return d;
}
__device__ __forceinline__ float silu_f(float x) {
    float e = __expf(-x);
    return __fdividef(x, 1.0f + e);
}

__device__ __forceinline__ void mma_bf16(
    float c[4], u32 a0, u32 a1, u32 a2, u32 a3, u32 b0, u32 b1)
{
    asm volatile(
        "mma.sync.aligned.m16n8k16.row.col.f32.bf16.bf16.f32 "
        "{%0,%1,%2,%3}, {%4,%5,%6,%7}, {%8,%9}, {%0,%1,%2,%3};"
        : "+f"(c[0]), "+f"(c[1]), "+f"(c[2]), "+f"(c[3])
        : "r"(a0), "r"(a1), "r"(a2), "r"(a3), "r"(b0), "r"(b1));
}

__device__ __forceinline__ void ldm_x4(u32 r[4], u32 addr) {
    asm volatile(
        "ldmatrix.sync.aligned.m8n8.x4.shared.b16 {%0,%1,%2,%3}, [%4];"
        : "=r"(r[0]), "=r"(r[1]), "=r"(r[2]), "=r"(r[3]) : "r"(addr));
}

__device__ __forceinline__ void cp16(u32 dst, const void* src) {
    asm volatile("cp.async.cg.shared.global [%0], [%1], 16;"
                 :: "r"(dst), "l"(src));
}
#define CP_COMMIT() asm volatile("cp.async.commit_group;" ::: "memory")
#define CP_WAIT(n)  asm volatile("cp.async.wait_group %0;" :: "n"(n) : "memory")

// ---------------- prep: merged transpose-split of 4 weight matrices ----------
__global__ __launch_bounds__(256) void split_weights(
    const float* __restrict__ W0, const float* __restrict__ W1,
    const float* __restrict__ W2, const float* __restrict__ W3,
    bf16* __restrict__ o0h, bf16* __restrict__ o0l,
    bf16* __restrict__ o1h, bf16* __restrict__ o1l,
    bf16* __restrict__ o2h, bf16* __restrict__ o2l,
    bf16* __restrict__ o3h, bf16* __restrict__ o3l)
{
    __shared__ float t[32][33];
    const int z = blockIdx.z;
    const float* W = (z == 0) ? W0 : (z == 1) ? W1 : (z == 2) ? W2 : W3;
    bf16* oh = (z == 0) ? o0h : (z == 1) ? o1h : (z == 2) ? o2h : o3h;
    bf16* ol = (z == 0) ? o0l : (z == 1) ? o1l : (z == 2) ? o2l : o3l;

    const int tx = threadIdx.x;
    const int ty = threadIdx.y;
    const int jb = blockIdx.x * 32;
    const int kb = blockIdx.y * 32;

#pragma unroll
    for (int i = 0; i < 4; i++)
        t[ty + i * 8][tx] = W[(size_t)(kb + ty + i * 8) * DIM + jb + tx];
    __syncthreads();

#pragma unroll
    for (int i = 0; i < 4; i++) {
        const float v = t[tx][ty + i * 8];
        const bf16 h = __float2bfloat16(v);
        const bf16 l = __float2bfloat16(v - __bfloat162float(h));
        const size_t o = (size_t)(jb + ty + i * 8) * DIM + kb + tx;
        oh[o] = h;
        ol[o] = l;
    }
}

// ---------------------------------------------------------------------------
// mma.sync GEMM: CTA 64x64, K chunks of 64 double-buffered, ldmatrix + HMMA.
// D = Ah@Bh + Ah@Bl + Al@Bh (fp32 regs).
// MODE 0: A f32 (split in staging, register path); f32 + hi/lo out
// MODE 1: hi/lo A via cp.async; hi/lo out (+extra)
// MODE 2: hi/lo A via cp.async; f32 out = (silu(acc+bias)+res)*scale
// ---------------------------------------------------------------------------
constexpr int LDT = 72;
constexpr int ARR = 64 * LDT;
constexpr int BUF = 4 * ARR;
constexpr int GSMEM = 2 * BUF * 2;    // 73728 bytes

template <int MODE>
__global__ __launch_bounds__(256) void gemm_mma(
    const float* __restrict__ A32,
    const bf16* __restrict__ Ah, const bf16* __restrict__ Al,
    const bf16* __restrict__ BTh, const bf16* __restrict__ BTl,
    const float* __restrict__ bias, const float* __restrict__ extra,
    const float* __restrict__ res, const float* __restrict__ scale_p,
    float* __restrict__ out_f32,
    bf16* __restrict__ out_h, bf16* __restrict__ out_l)
{
    extern __shared__ bf16 sm[];
    const u32 smb = (u32)__cvta_generic_to_shared(sm);

    const int tid  = threadIdx.x;
    const int wid  = tid >> 5;
    const int lane = tid & 31;
    const int wm   = wid & 1;
    const int wn   = wid >> 1;
    const int m0   = blockIdx.y * 64;
    const int n0   = blockIdx.x * 64;

    const int lr = lane >> 2;
    const int lc = (lane & 3) * 2;

    const int s0r = tid >> 3, s0v = tid & 7;
    const int s1r = s0r + 32, s1v = s0v;

    float acc[2][2][4];
#pragma unroll
    for (int i = 0; i < 2; i++)
#pragma unroll
        for (int j = 0; j < 2; j++)
#pragma unroll
            for (int q = 0; q < 4; q++) acc[i][j][q] = 0.0f;

    const int a_row = wm * 32 + ((lane >> 3) & 1) * 8 + (lane & 7);
    const int a_kof = (lane >> 4) << 3;
    const int b_row = wn * 16 + ((lane >> 4) << 3) + (lane & 7);
    const int b_kof = ((lane >> 3) & 1) << 3;

    const u32 so0 = (u32)(s0r * LDT + s0v * 8) * 2;   // byte offsets
    const u32 so1 = (u32)(s1r * LDT + s1v * 8) * 2;

    // MODE 0 register staging state
    float4 pa32[4];
    uint4  pbh[2], pbl[2];

    auto issue_chunk_async = [&](int c, int buf) {   // MODE != 0
        const int k0 = c * 64;
        const u32 ah_b = smb + (buf * BUF) * 2;
        const u32 al_b = ah_b + ARR * 2;
        const u32 bh_b = ah_b + 2 * ARR * 2;
        const u32 bl_b = ah_b + 3 * ARR * 2;
        const size_t ga0 = (size_t)(m0 + s0r) * DIM + k0 + s0v * 8;
        const size_t ga1 = (size_t)(m0 + s1r) * DIM + k0 + s1v * 8;
        const size_t gb0 = (size_t)(n0 + s0r) * DIM + k0 + s0v * 8;
        const size_t gb1 = (size_t)(n0 + s1r) * DIM + k0 + s1v * 8;
        cp16(ah_b + so0, Ah + ga0);
        cp16(ah_b + so1, Ah + ga1);
        cp16(al_b + so0, Al + ga0);
        cp16(al_b + so1, Al + ga1);
        cp16(bh_b + so0, BTh + gb0);
        cp16(bh_b + so1, BTh + gb1);
        cp16(bl_b + so0, BTl + gb0);
        cp16(bl_b + so1, BTl + gb1);
        CP_COMMIT();
    };

    auto fetch_chunk_m0 = [&](int c) {               // MODE 0
        const int k0 = c * 64;
        pa32[0] = *(const float4*)(A32 + (size_t)(m0 + s0r) * DIM + k0 + s0v * 8);
        pa32[1] = *(const float4*)(A32 + (size_t)(m0 + s0r) * DIM + k0 + s0v * 8 + 4);
        pa32[2] = *(const float4*)(A32 + (size_t)(m0 + s1r) * DIM + k0 + s1v * 8);
        pa32[3] = *(const float4*)(A32 + (size_t)(m0 + s1r) * DIM + k0 + s1v * 8 + 4);
        pbh[0] = *(const uint4*)(BTh + (size_t)(n0 + s0r) * DIM + k0 + s0v * 8);
        pbl[0] = *(const uint4*)(BTl + (size_t)(n0 + s0r) * DIM + k0 + s0v * 8);
        pbh[1] = *(const uint4*)(BTh + (size_t)(n0 + s1r) * DIM + k0 + s1v * 8);
        pbl[1] = *(const uint4*)(BTl + (size_t)(n0 + s1r) * DIM + k0 + s1v * 8);
    };

    auto store_chunk_m0 = [&](int buf) {
        bf16* AhS = sm + buf * BUF;
        bf16* AlS = AhS + ARR;
        bf16* BhS = AhS + 2 * ARR;
        bf16* BlS = AhS + 3 * ARR;
        bf16 h[8], l[8];
        float v[8] = { pa32[0].x, pa32[0].y, pa32[0].z, pa32[0].w,
                       pa32[1].x, pa32[1].y, pa32[1].z, pa32[1].w };
#pragma unroll
        for (int j = 0; j < 8; j++) {
            h[j] = __float2bfloat16(v[j]);
            l[j] = __float2bfloat16(v[j] - __bfloat162float(h[j]));
        }
        *(uint4*)&AhS[s0r * LDT + s0v * 8] = *(uint4*)h;
        *(uint4*)&AlS[s0r * LDT + s0v * 8] = *(uint4*)l;
        float v2[8] = { pa32[2].x, pa32[2].y, pa32[2].z, pa32[2].w,
                        pa32[3].x, pa32[3].y, pa32[3].z, pa32[3].w };
#pragma unroll
        for (int j = 0; j < 8; j++) {
            h[j] = __float2bfloat16(v2[j]);
            l[j] = __float2bfloat16(v2[j] - __bfloat162float(h[j]));
        }
        *(uint4*)&AhS[s1r * LDT + s1v * 8] = *(uint4*)h;
        *(uint4*)&AlS[s1r * LDT + s1v * 8] = *(uint4*)l;
        *(uint4*)&BhS[s0r * LDT + s0v * 8] = pbh[0];
        *(uint4*)&BlS[s0r * LDT + s0v * 8] = pbl[0];
        *(uint4*)&BhS[s1r * LDT + s1v * 8] = pbh[1];
        *(uint4*)&BlS[s1r * LDT + s1v * 8] = pbl[1];
    };

    auto compute_chunk = [&](int buf) {
        const u32 ah_b = smb + (buf * BUF) * 2;
        const u32 al_b = ah_b + ARR * 2;
        const u32 bh_b = ah_b + 2 * ARR * 2;
        const u32 bl_b = ah_b + 3 * ARR * 2;
#pragma unroll
        for (int ks = 0; ks < 4; ks++) {
            const int kb = ks * 16;
            u32 ah[2][4], al[2][4], bh[4], bl[4];
#pragma unroll
            for (int mt = 0; mt < 2; mt++) {
                const u32 aoff = (u32)((a_row + mt * 16) * LDT + kb + a_kof) * 2;
                ldm_x4(ah[mt], ah_b + aoff);
                ldm_x4(al[mt], al_b + aoff);
            }
            const u32 boff = (u32)(b_row * LDT + kb + b_kof) * 2;
            ldm_x4(bh, bh_b + boff);
            ldm_x4(bl, bl_b + boff);
#pragma unroll
            for (int mt = 0; mt < 2; mt++)
#pragma unroll
                for (int nt = 0; nt < 2; nt++) {
                    mma_bf16(acc[mt][nt], ah[mt][0], ah[mt][1], ah[mt][2], ah[mt][3],
                             bh[nt * 2], bh[nt * 2 + 1]);
                    mma_bf16(acc[mt][nt], ah[mt][0], ah[mt][1], ah[mt][2], ah[mt][3],
                             bl[nt * 2], bl[nt * 2 + 1]);
                    mma_bf16(acc[mt][nt], al[mt][0], al[mt][1], al[mt][2], al[mt][3],
                             bh[nt * 2], bh[nt * 2 + 1]);
                }
        }
    };

    if (MODE == 0) {
        fetch_chunk_m0(0);
        store_chunk_m0(0);
        __syncthreads();
        for (int c = 0; c < 4; c++) {
            const int buf = c & 1;
            if (c < 3) fetch_chunk_m0(c + 1);
            compute_chunk(buf);
            if (c < 3) store_chunk_m0(buf ^ 1);
            __syncthreads();
        }
    } else {
        issue_chunk_async(0, 0);
        for (int c = 0; c < 4; c++) {
            const int buf = c & 1;
            if (c < 3) {
                issue_chunk_async(c + 1, buf ^ 1);
                CP_WAIT(1);
            } else {
                CP_WAIT(0);
            }
            __syncthreads();
            compute_chunk(buf);
            __syncthreads();
        }
    }

    // ---- epilogue ----
    float sc = 1.0f;
    if (MODE == 2) sc = *scale_p;

#pragma unroll
    for (int mt = 0; mt < 2; mt++)
#pragma unroll
        for (int nt = 0; nt < 2; nt++) {
            const int col = n0 + wn * 16 + nt * 8 + lc;
            const float2 bv = *(const float2*)(bias + col);
#pragma unroll
            for (int half = 0; half < 2; half++) {
                const int row = m0 + wm * 32 + mt * 16 + lr + half * 8;
                const size_t off = (size_t)row * DIM + col;
                float w0 = acc[mt][nt][2 * half + 0] + bv.x;
                float w1 = acc[mt][nt][2 * half + 1] + bv.y;
                if (MODE == 1) {
                    float2 e = *(const float2*)(extra + off);
                    w0 += e.x; w1 += e.y;
                }
                float o0 = silu_f(w0), o1 = silu_f(w1);
                if (MODE == 2) {
                    float2 rv = *(const float2*)(res + off);
                    o0 = (o0 + rv.x) * sc;
                    o1 = (o1 + rv.y) * sc;
                }
                if (MODE != 1)
                    *(float2*)(out_f32 + off) = make_float2(o0, o1);
                if (MODE != 2) {
                    bf16 h0 = __float2bfloat16(o0);
                    bf16 h1 = __float2bfloat16(o1);
                    bf16 l0 = __float2bfloat16(o0 - __bfloat162float(h0));
                    bf16 l1 = __float2bfloat16(o1 - __bfloat162float(h1));
                    bf16 hp[2] = { h0, h1 }, lp[2] = { l0, l1 };
                    *(u32*)(out_h + off) = *(u32*)hp;
                    *(u32*)(out_l + off) = *(u32*)lp;
                }
            }
        }
}

// ---------------------------------------------------------------------------
// Pair kernel: 4 electrons per block, 256 threads (higher occupancy).
// ---------------------------------------------------------------------------
constexpr int NPB   = 4;
constexpr int PAIRS = NPB * NNB;   // 96

__global__ __launch_bounds__(256) void pair_kernel(
    const float* __restrict__ elec1,
    const float* __restrict__ r,
    const float* __restrict__ r_nb,
    const int*   __restrict__ s,
    const int*   __restrict__ s_nb,
    const float* __restrict__ hinit_nb,
    const float* __restrict__ ee_scales,
    const float* __restrict__ ee_kernel,
    const float* __restrict__ ee_bias,
    const float* __restrict__ Wf,
    const float* __restrict__ bf,
    const float* __restrict__ Wsame,
    const float* __restrict__ Wdiff,
    float* __restrict__ hinit_msg)
{
    __shared__ __align__(16) float beta_s[PAIRS][F1];
    __shared__ float maskf_s[PAIRS];
    __shared__ u64  wd2_s [8][DIM];
    __shared__ u64  wsd2_s[8][DIM];
    __shared__ float eek_s[4 * F0];
    __shared__ float eeb_s[F0];
    __shared__ float wf_s[(F0 + NENV) * F1];
    __shared__ float bfv_s[F1];
    __shared__ float scl_s[NENV];

    const int tid = threadIdx.x;
    const int n0  = blockIdx.x * NPB;

    for (int i = tid; i < 4 * F0; i += 256) eek_s[i] = ee_kernel[i];
    for (int i = tid; i < F0; i += 256)     eeb_s[i] = ee_bias[i];
    for (int i = tid; i < (F0 + NENV) * F1; i += 256) wf_s[i] = Wf[i];
    if (tid < F1)   bfv_s[tid] = bf[tid];
    if (tid < NENV) scl_s[tid] = ee_scales[tid];

#pragma unroll
    for (int i = 0; i < 8; i++) {
        float d0 = Wdiff[(2 * i + 0) * DIM + tid];
        float d1 = Wdiff[(2 * i + 1) * DIM + tid];
        float s0 = Wsame[(2 * i + 0) * DIM + tid] - d0;
        float s1 = Wsame[(2 * i + 1) * DIM + tid] - d1;
        wd2_s [i][tid] = pk2(d0, d1);
        wsd2_s[i][tid] = pk2(s0, s1);
    }
    __syncthreads();

    if (tid < PAIRS) {
        const int nl = tid / NNB;
        const int k  = tid % NNB;
        const int n  = n0 + nl;

        const float rx = r[n * 3 + 0];
        const float ry = r[n * 3 + 1];
        const float rz = r[n * 3 + 2];
        const float* rn = r_nb + (size_t)(n * NNB + k) * 3;
        const float dx = rn[0] - rx;
        const float dy = rn[1] - ry;
        const float dz = rn[2] - rz;
        const float dist = sqrtf(dx * dx + dy * dy + dz * dz + 1e-12f);

        float feats[4] = { dist, dx, dy, dz };
        float h[F0];
#pragma unroll
        for (int j = 0; j < F0; j++) {
            float t = eeb_s[j];
#pragma unroll
            for (int f = 0; f < 4; f++) t += feats[f] * eek_s[f * F0 + j];
            h[j] = silu_f(t);
        }
        float env[NENV];
#pragma unroll
        for (int e = 0; e < NENV; e++) {
            float q = __fdividef(dist, scl_s[e]);
            env[e] = __expf(-q * q);
        }
        const float xx  = dist * (1.0f / CUTOFF);
        const float cut = (dist < CUTOFF)
                        ? (1.0f - xx) * (1.0f - xx) * (1.0f + 2.0f * xx)
                        : 0.0f;
#pragma unroll
        for (int i = 0; i < F1; i++) {
            float b = bfv_s[i];
#pragma unroll
            for (int j = 0; j < F0; j++)   b += h[j]   * wf_s[j * F1 + i];
#pragma unroll
            for (int e = 0; e < NENV; e++) b += env[e] * wf_s[(F0 + e) * F1 + i];
            beta_s[tid][i] = b * cut;
        }
        maskf_s[tid] = (s[n] == s_nb[n * NNB + k]) ? 1.0f : 0.0f;
    }
    __syncthreads();

    const int d = tid;
#pragma unroll
    for (int nl = 0; nl < NPB; nl++) {
        const int n = n0 + nl;
        const float e1 = elec1[(size_t)n * DIM + d];
        const float* hb = hinit_nb + ((size_t)n * NNB) * DIM + d;

        float uu[NNB];
#pragma unroll
        for (int k = 0; k < NNB; k++) uu[k] = e1 + hb[(size_t)k * DIM];
#pragma unroll
        for (int k = 0; k < NNB; k++) uu[k] = silu_f(uu[k]);

        u64 vall[8], vsm[8];
#pragma unroll
        for (int i = 0; i < 8; i++) { vall[i] = 0ull; vsm[i] = 0ull; }

#pragma unroll
        for (int k = 0; k < NNB; k++) {
            const int pair = nl * NNB + k;
            const float u  = uu[k];
            const float um = u * maskf_s[pair];
            const u64 u2   = pk2(u, u);
            const u64 um2  = pk2(um, um);
            const u64* bp  = (const u64*)beta_s[pair];
#pragma unroll
            for (int i = 0; i < 8; i++) {
                vall[i] = f2fma(u2,  bp[i], vall[i]);
                vsm[i]  = f2fma(um2, bp[i], vsm[i]);
            }
        }

        u64 r2 = 0ull;
#pragma unroll
        for (int i = 0; i < 8; i++) r2 = f2fma(wd2_s[i][d],  vall[i], r2);
#pragma unroll
        for (int i = 0; i < 8; i++) r2 = f2fma(wsd2_s[i][d], vsm[i],  r2);
        float2 rr = upk2(r2);
        hinit_msg[(size_t)n * DIM + d] = rr.x + rr.y;
    }
}

// ---------------------------------------------------------------------------
extern "C" void kernel_launch(void* const* d_in, const int* in_sizes, int n_in,
                              void* d_out, int out_size)
{
    const float* elec     = (const float*)d_in[0];
    const float* msg      = (const float*)d_in[1];
    const float* r        = (const float*)d_in[2];
    const float* r_nb     = (const float*)d_in[3];
    const int*   s        = (const int*)  d_in[4];
    const int*   s_nb     = (const int*)  d_in[5];
    const float* hinit_nb = (const float*)d_in[6];
    const float* W_in     = (const float*)d_in[7];
    const float* b_in     = (const float*)d_in[8];
    const float* ee_scales= (const float*)d_in[9];
    const float* ee_kernel= (const float*)d_in[10];
    const float* ee_bias  = (const float*)d_in[11];
    const float* Wf       = (const float*)d_in[12];
    const float* bf       = (const float*)d_in[13];
    const float* Wsame    = (const float*)d_in[14];
    const float* Wdiff    = (const float*)d_in[15];
    const float* W1       = (const float*)d_in[16];
    const float* b1       = (const float*)d_in[17];
    const float* W2       = (const float*)d_in[18];
    const float* b2       = (const float*)d_in[19];
    const float* W3       = (const float*)d_in[20];
    const float* b3       = (const float*)d_in[21];
    const float* scale    = (const float*)d_in[22];

    float* out = (float*)d_out;

    float *e1, *hmsg;
    bf16 *e1h, *e1l, *t1h, *t1l, *t2h, *t2l;
    bf16 *w0h, *w0l, *w1h, *w1l, *w2h, *w2l, *w3h, *w3l;
    cudaGetSymbolAddress((void**)&e1,   g_e1);
    cudaGetSymbolAddress((void**)&hmsg, g_hmsg);
    cudaGetSymbolAddress((void**)&e1h, g_e1h); cudaGetSymbolAddress((void**)&e1l, g_e1l);
    cudaGetSymbolAddress((void**)&t1h, g_t1h); cudaGetSymbolAddress((void**)&t1l, g_t1l);
    cudaGetSymbolAddress((void**)&t2h, g_t2h); cudaGetSymbolAddress((void**)&t2l, g_t2l);
    cudaGetSymbolAddress((void**)&w0h, g_w0h); cudaGetSymbolAddress((void**)&w0l, g_w0l);
    cudaGetSymbolAddress((void**)&w1h, g_w1h); cudaGetSymbolAddress((void**)&w1l, g_w1l);
    cudaGetSymbolAddress((void**)&w2h, g_w2h); cudaGetSymbolAddress((void**)&w2l, g_w2l);
    cudaGetSymbolAddress((void**)&w3h, g_w3h); cudaGetSymbolAddress((void**)&w3l, g_w3l);

    cudaFuncSetAttribute(gemm_mma<0>, cudaFuncAttributeMaxDynamicSharedMemorySize, GSMEM);
    cudaFuncSetAttribute(gemm_mma<1>, cudaFuncAttributeMaxDynamicSharedMemorySize, GSMEM);
    cudaFuncSetAttribute(gemm_mma<2>, cudaFuncAttributeMaxDynamicSharedMemorySize, GSMEM);

    split_weights<<<dim3(8, 8, 4), dim3(32, 8)>>>(
        W_in, W1, W2, W3, w0h, w0l, w1h, w1l, w2h, w2l, w3h, w3l);

    dim3 ggrid(DIM / 64, N_ELEC / 64);   // (4, 128) = 512 CTAs

    gemm_mma<0><<<ggrid, 256, GSMEM>>>(elec, nullptr, nullptr, w0h, w0l, b_in,
                                       nullptr, nullptr, nullptr, e1, e1h, e1l);

    pair_kernel<<<N_ELEC / NPB, 256>>>(e1, r, r_nb, s, s_nb, hinit_nb,
                                       ee_scales, ee_kernel, ee_bias, Wf, bf,
                                       Wsame, Wdiff, hmsg);

    gemm_mma<1><<<ggrid, 256, GSMEM>>>(nullptr, e1h, e1l, w1h, w1l, b1,
                                       hmsg, nullptr, nullptr, nullptr, t1h, t1l);
    gemm_mma<1><<<ggrid, 256, GSMEM>>>(nullptr, t1h, t1l, w2h, w2l, b2,
                                       msg, nullptr, nullptr, nullptr, t2h, t2l);
    gemm_mma<2><<<ggrid, 256, GSMEM>>>(nullptr, t2h, t2l, w3h, w3l, b3,
                                       nullptr, e1, scale, out, nullptr, nullptr);
}